// round 15
// baseline (speedup 1.0000x reference)
#include <cuda_runtime.h>
#include <cuda_fp16.h>
#include <cstdint>
#include <cstddef>

// Problem constants
#define N_NODES 50000
#define N_PAD   50048
#define KNBR    32
#define FDIM    128
#define EDIM    8
#define KDIM    1024          // FDIM * EDIM

// G as fp16, rows [i][kk], kk = n*128 + l  (zero-init; rows >= 50000 stay 0)
__device__ __half g_h[(size_t)N_PAD * KDIM];   // 102.5 MB
// W rearranged to [kk][m] fp16
__device__ __half wt_h[KDIM * FDIM];
// fp16 copy of nodes (gather table, L2-resident 12.8 MB)
__device__ __half nodes_h[(size_t)N_NODES * FDIM];

// ---------------------------------------------------------------------------
// helpers
// ---------------------------------------------------------------------------
__device__ __forceinline__ uint32_t smem_u32(const void* p) {
    uint32_t a;
    asm("{ .reg .u64 t; cvta.to.shared.u64 t, %1; cvt.u32.u64 %0, t; }" : "=r"(a) : "l"(p));
    return a;
}

__device__ __forceinline__ void cp_async16(uint32_t dst, const void* src) {
    asm volatile("cp.async.cg.shared.global [%0], [%1], 16;" :: "r"(dst), "l"(src));
}
__device__ __forceinline__ void cp_commit() {
    asm volatile("cp.async.commit_group;");
}

__device__ __forceinline__ void ldm_x4(uint32_t* r, uint32_t addr) {
    asm volatile("ldmatrix.sync.aligned.m8n8.x4.shared.b16 {%0,%1,%2,%3}, [%4];"
                 : "=r"(r[0]), "=r"(r[1]), "=r"(r[2]), "=r"(r[3]) : "r"(addr));
}
__device__ __forceinline__ void ldm_x4t(uint32_t* r, uint32_t addr) {
    asm volatile("ldmatrix.sync.aligned.m8n8.x4.trans.shared.b16 {%0,%1,%2,%3}, [%4];"
                 : "=r"(r[0]), "=r"(r[1]), "=r"(r[2]), "=r"(r[3]) : "r"(addr));
}

__device__ __forceinline__ void mma_f16(float* c, const uint32_t* a, const uint32_t* b) {
    asm volatile(
        "mma.sync.aligned.m16n8k16.row.col.f32.f16.f16.f32 "
        "{%0,%1,%2,%3}, {%4,%5,%6,%7}, {%8,%9}, {%0,%1,%2,%3};"
        : "+f"(c[0]), "+f"(c[1]), "+f"(c[2]), "+f"(c[3])
        : "r"(a[0]), "r"(a[1]), "r"(a[2]), "r"(a[3]), "r"(b[0]), "r"(b[1]));
}

// ---------------------------------------------------------------------------
// Kernel 0a: w (F,F,E) -> wt_h [kk][m],  kk = n*128 + l
// ---------------------------------------------------------------------------
__global__ void transpose_w_kernel(const float* __restrict__ w) {
    int idx = blockIdx.x * blockDim.x + threadIdx.x;
    if (idx >= KDIM * FDIM) return;
    int kk = idx >> 7;          // n*128 + l
    int m  = idx & 127;
    int n  = kk >> 7;
    int l  = kk & 127;
    wt_h[idx] = __float2half_rn(w[(l * FDIM + m) * EDIM + n]);
}

// ---------------------------------------------------------------------------
// Kernel 0b: nodes fp32 -> fp16 table
// ---------------------------------------------------------------------------
__global__ void convert_nodes_kernel(const float* __restrict__ nodes) {
    int idx = blockIdx.x * blockDim.x + threadIdx.x;   // 4 elements each
    if (idx * 4 >= N_NODES * FDIM) return;
    const float4 v = *(const float4*)(nodes + idx * 4);
    __half2 a = __floats2half2_rn(v.x, v.y);
    __half2 b = __floats2half2_rn(v.z, v.w);
    *(uint2*)&nodes_h[(size_t)idx * 4] = make_uint2(*(uint32_t*)&a, *(uint32_t*)&b);
}

// ---------------------------------------------------------------------------
// Kernel 1: stage 1 on tensor cores, PERSISTENT + PIPELINED.
// One warp per node per iteration; warp strides over nodes with ping-pong X
// buffers: gather(n+1) in flight while computing node n.
//   D[l, e] = sum_j X[j, l] * E[j, e]   (M=128, N=8, K=32)
// Mappings identical to the proven one-shot version:
//   X tile: row j = lane, 16 chunks of 16B, swizzle chunk' = c ^ (row & 15)
//   A frags: ldmatrix.trans; E frags: ldmatrix.trans on 32x16B tile
// Store path: stage D into the dead X buffer (G layout), then 4x STG.128.
// ---------------------------------------------------------------------------
#define S1_GRID    148
#define S1_NWARPS  (S1_GRID * 8)              // 1184
#define S1_WSTRIDE 16896                      // 2 x 8KB X + 512B E
#define S1_SMEM    (8 * S1_WSTRIDE)           // 132 KB -> 1 CTA/SM

__global__ void __launch_bounds__(256, 1) stage1_tensor_kernel(
    const int* __restrict__ nlist,
    const float* __restrict__ edges)
{
    extern __shared__ __align__(256) char smem[];
    const int tid  = threadIdx.x;
    const int lane = tid & 31;
    const int wid  = tid >> 5;

    char* wb = smem + wid * S1_WSTRIDE;
    const uint32_t xb0 = smem_u32(wb);            // X buffer 0 (8 KB)
    const uint32_t xb1 = xb0 + 8192;              // X buffer 1 (8 KB)
    const uint32_t ebs = xb0 + 16384;             // E tile (512 B)

    // A-frag lane mapping (trans), constant per lane
    const int krow_lo = (lane & 7) + ((lane >> 4) & 1) * 8;
    const int mc8     = (lane >> 3) & 1;
    // D -> G mapping constants
    const int e0 = (lane & 3) * 2;

    int i = blockIdx.x * 8 + wid;                 // first node for this warp

    // ---- prologue: node i's E row (regs) + neighbor + gather -> buf 0 ----
    float4 ea, eb;
    {
        const float4* e4 = (const float4*)(edges + (size_t)i * (KNBR * EDIM));
        ea = e4[lane * 2 + 0];
        eb = e4[lane * 2 + 1];
    }
    {
        int nb = nlist[(size_t)i * KNBR + lane];
        nb = nb < 0 ? 0 : (nb >= N_NODES ? N_NODES - 1 : nb);
        const __half* src = nodes_h + (size_t)nb * FDIM;
        const uint32_t rowbase = xb0 + lane * 256;
#pragma unroll
        for (int c = 0; c < 16; c++)
            cp_async16(rowbase + ((c ^ (lane & 15)) << 4), src + c * 8);
    }
    cp_commit();

    int buf = 0;

#pragma unroll 1
    for (; i < N_NODES; ) {
        const int inext = i + S1_NWARPS;
        const uint32_t xb_cur = buf ? xb1 : xb0;
        const uint32_t xb_nxt = buf ? xb0 : xb1;

        // ---- prefetch next node: E regs + neighbor gather into other buf ----
        float4 na = ea, nb4 = eb;   // placeholders keep regs defined
        if (inext < N_NODES) {
            const float4* e4 = (const float4*)(edges + (size_t)inext * (KNBR * EDIM));
            na  = e4[lane * 2 + 0];
            nb4 = e4[lane * 2 + 1];
            int nb = nlist[(size_t)inext * KNBR + lane];
            nb = nb < 0 ? 0 : (nb >= N_NODES ? N_NODES - 1 : nb);
            const __half* src = nodes_h + (size_t)nb * FDIM;
            const uint32_t rowbase = xb_nxt + lane * 256;
#pragma unroll
            for (int c = 0; c < 16; c++)
                cp_async16(rowbase + ((c ^ (lane & 15)) << 4), src + c * 8);
        }
        cp_commit();   // always: keeps group FIFO aligned

        // ---- stage E(i) to smem ----
        {
            __half2 h0 = __floats2half2_rn(ea.x, ea.y);
            __half2 h1 = __floats2half2_rn(ea.z, ea.w);
            __half2 h2 = __floats2half2_rn(eb.x, eb.y);
            __half2 h3 = __floats2half2_rn(eb.z, eb.w);
            *(uint4*)(wb + 16384 + lane * 16) =
                make_uint4(*(uint32_t*)&h0, *(uint32_t*)&h1,
                           *(uint32_t*)&h2, *(uint32_t*)&h3);
        }
        __syncwarp();

        // ---- wait for gather(i); gather(inext) stays in flight ----
        asm volatile("cp.async.wait_group 1;");
        __syncwarp();

        // ---- compute ----
        uint32_t ebf[4];
        ldm_x4t(ebf, ebs + lane * 16);

        float acc[8][4];
#pragma unroll
        for (int mt = 0; mt < 8; mt++)
#pragma unroll
            for (int q = 0; q < 4; q++) acc[mt][q] = 0.f;

#pragma unroll
        for (int mt = 0; mt < 8; mt++) {
            const int ch = mt * 2 + mc8;
            uint32_t a0[4], a1[4];
            {
                const int kr = krow_lo;
                ldm_x4t(a0, xb_cur + kr * 256 + ((ch ^ (kr & 15)) << 4));
            }
            {
                const int kr = krow_lo + 16;
                ldm_x4t(a1, xb_cur + kr * 256 + ((ch ^ (kr & 15)) << 4));
            }
            mma_f16(acc[mt], a0, ebf + 0);
            mma_f16(acc[mt], a1, ebf + 2);
        }

        // ---- store: stage D into the (dead) current X buffer in G layout ----
        {
            __half* gs = (__half*)(wb + (buf ? 8192 : 0));
#pragma unroll
            for (int mt = 0; mt < 8; mt++) {
                const int l0 = mt * 16 + (lane >> 2);
                gs[e0 * FDIM + l0]           = __float2half_rn(acc[mt][0]);
                gs[(e0 + 1) * FDIM + l0]     = __float2half_rn(acc[mt][1]);
                gs[e0 * FDIM + l0 + 8]       = __float2half_rn(acc[mt][2]);
                gs[(e0 + 1) * FDIM + l0 + 8] = __float2half_rn(acc[mt][3]);
            }
            __syncwarp();
            // coalesced write-out: lane owns 64B of the 2KB G row
            const uint4* gsv = (const uint4*)gs;
            uint4* gdst = (uint4*)(g_h + (size_t)i * KDIM + lane * 32);
#pragma unroll
            for (int q = 0; q < 4; q++)
                gdst[q] = gsv[lane * 4 + q];
        }
        // note: gather(inext) targets the OTHER buffer; the staging reads above
        // complete (LDS latency ~29cyc) long before any in-flight cp.async
        // data (~600cyc) could land — and they are to different buffers anyway.

        ea = na; eb = nb4;
        i = inext;
        buf ^= 1;
    }
}

// ---------------------------------------------------------------------------
// Kernel 2: mma.sync fp16 GEMM (unchanged, proven).
// BM=64 x BN=128, 4-stage cp.async, 3 CTAs/SM, reversed tile order.
// ---------------------------------------------------------------------------
#define BM        64
#define KC        32
#define NKCHUNKS  (KDIM / KC)         // 32
#define OFF_A     0
#define OFF_B     4096
#define BUF_BYTES 12288               // 4K (A) + 8K (B)
#define NSTAGES   4
#define SMEM_DYN  (NSTAGES * BUF_BYTES)   // 48 KB
#define NBLOCKS_M ((N_NODES + BM - 1) / BM)   // 782

__global__ void __launch_bounds__(256, 3) stage2_mma_kernel(
    const float* __restrict__ inv_degree,
    float* __restrict__ out)
{
    extern __shared__ __align__(128) char smem[];
    const uint32_t sbase = smem_u32(smem);

    const int tid    = threadIdx.x;
    const int lane   = tid & 31;
    const int wid    = tid >> 5;
    const int warp_m = wid & 3;
    const int warp_n = wid >> 2;
    const int m0     = (NBLOCKS_M - 1 - blockIdx.x) * BM;

    float acc[8][4];
#pragma unroll
    for (int nt = 0; nt < 8; nt++)
#pragma unroll
        for (int q = 0; q < 4; q++) acc[nt][q] = 0.f;

    auto load_chunk = [&](int kc, int b) {
        if (kc < NKCHUNKS) {
            const uint32_t sb = sbase + b * BUF_BYTES;
            {
                const int row = tid >> 2;
                const int c   = tid & 3;
                const uint32_t so = row * 64 + ((c ^ ((row >> 1) & 3)) << 4);
                const size_t ge = (size_t)(m0 + row) * KDIM + kc * KC + c * 8;
                cp_async16(sb + OFF_A + so, g_h + ge);
            }
#pragma unroll
            for (int it = 0; it < 2; it++) {
                const int cb  = tid + it * 256;
                const int row = cb >> 4;
                const int c   = cb & 15;
                const uint32_t so = row * 256 + ((c ^ (row & 15)) << 4);
                const size_t ge = (size_t)(kc * KC + row) * FDIM + c * 8;
                cp_async16(sb + OFF_B + so, wt_h + ge);
            }
        }
        cp_commit();
    };

    load_chunk(0, 0);
    load_chunk(1, 1);
    load_chunk(2, 2);

#pragma unroll 1
    for (int kc = 0; kc < NKCHUNKS; kc++) {
        asm volatile("cp.async.wait_group 2;");
        __syncthreads();

        load_chunk(kc + 3, (kc + 3) % NSTAGES);

        const uint32_t sb = sbase + (kc % NSTAGES) * BUF_BYTES;

#pragma unroll
        for (int k16 = 0; k16 < 2; k16++) {
            uint32_t af[4];
            const int rA  = (lane & 7) + ((lane >> 3) & 1) * 8;
            const int kch = k16 * 2 + (lane >> 4);
            {
                const int row = warp_m * 16 + rA;
                const uint32_t off = row * 64 + ((kch ^ ((row >> 1) & 3)) << 4);
                ldm_x4(af, sb + OFF_A + off);
            }
            const int rB = k16 * 16 + (lane & 7) + ((lane >> 3) & 1) * 8;
#pragma unroll
            for (int nt16 = 0; nt16 < 4; nt16++) {
                const int nch = warp_n * 8 + nt16 * 2 + (lane >> 4);
                const uint32_t off = rB * 256 + ((nch ^ (rB & 15)) << 4);
                uint32_t bf[4];
                ldm_x4t(bf, sb + OFF_B + off);
                mma_f16(acc[nt16 * 2 + 0], af, bf + 0);
                mma_f16(acc[nt16 * 2 + 1], af, bf + 2);
            }
        }
    }

    {
        const int r0 = m0 + warp_m * 16 + (lane >> 2);
        const int r1 = r0 + 8;
        const float s0 = (r0 < N_NODES) ? inv_degree[r0] : 0.f;
        const float s1 = (r1 < N_NODES) ? inv_degree[r1] : 0.f;
#pragma unroll
        for (int nt = 0; nt < 8; nt++) {
            const int col = warp_n * 64 + nt * 8 + (lane & 3) * 2;
            if (r0 < N_NODES) {
                float2 o = make_float2(acc[nt][0] * s0, acc[nt][1] * s0);
                *(float2*)(out + (size_t)r0 * FDIM + col) = o;
            }
            if (r1 < N_NODES) {
                float2 o = make_float2(acc[nt][2] * s1, acc[nt][3] * s1);
                *(float2*)(out + (size_t)r1 * FDIM + col) = o;
            }
        }
    }
}

// ---------------------------------------------------------------------------
// Launch. Inputs identified BY ELEMENT COUNT (all five distinct).
// ---------------------------------------------------------------------------
extern "C" void kernel_launch(void* const* d_in, const int* in_sizes, int n_in,
                              void* d_out, int out_size) {
    const float* nodes      = nullptr;
    const int*   nlist      = nullptr;
    const float* edges      = nullptr;
    const float* inv_degree = nullptr;
    const float* w          = nullptr;

    for (int i = 0; i < n_in; i++) {
        switch (in_sizes[i]) {
            case 6400000:  nodes      = (const float*)d_in[i]; break;
            case 1600000:  nlist      = (const int*)d_in[i];   break;
            case 12800000: edges      = (const float*)d_in[i]; break;
            case 50000:    inv_degree = (const float*)d_in[i]; break;
            case 131072:   w          = (const float*)d_in[i]; break;
            default: break;
        }
    }
    if (!nodes || !nlist || !edges || !inv_degree || !w) return;

    float* out = (float*)d_out;

    cudaFuncSetAttribute(stage1_tensor_kernel,
                         cudaFuncAttributeMaxDynamicSharedMemorySize, S1_SMEM);
    cudaFuncSetAttribute(stage2_mma_kernel,
                         cudaFuncAttributeMaxDynamicSharedMemorySize, SMEM_DYN);

    transpose_w_kernel<<<(KDIM * FDIM + 255) / 256, 256>>>(w);
    convert_nodes_kernel<<<(N_NODES * FDIM / 4 + 255) / 256, 256>>>(nodes);
    stage1_tensor_kernel<<<S1_GRID, 256, S1_SMEM>>>(nlist, edges);
    stage2_mma_kernel<<<NBLOCKS_M, 256, SMEM_DYN>>>(inv_degree, out);
}

// round 16
// speedup vs baseline: 1.6155x; 1.6155x over previous
#include <cuda_runtime.h>
#include <cuda_fp16.h>
#include <cstdint>
#include <cstddef>

// Problem constants
#define N_NODES 50000
#define N_PAD   50048
#define KNBR    32
#define FDIM    128
#define EDIM    8
#define KDIM    1024          // FDIM * EDIM

// G as fp16, rows [i][kk], kk = n*128 + l  (zero-init; rows >= 50000 stay 0)
__device__ __half g_h[(size_t)N_PAD * KDIM];   // 102.5 MB
// W rearranged to [kk][m] fp16
__device__ __half wt_h[KDIM * FDIM];
// fp16 copy of nodes (gather table, L2-resident 12.8 MB)
__device__ __half nodes_h[(size_t)N_NODES * FDIM];

// ---------------------------------------------------------------------------
// helpers
// ---------------------------------------------------------------------------
__device__ __forceinline__ uint32_t smem_u32(const void* p) {
    uint32_t a;
    asm("{ .reg .u64 t; cvta.to.shared.u64 t, %1; cvt.u32.u64 %0, t; }" : "=r"(a) : "l"(p));
    return a;
}

__device__ __forceinline__ void cp_async16(uint32_t dst, const void* src) {
    asm volatile("cp.async.cg.shared.global [%0], [%1], 16;" :: "r"(dst), "l"(src));
}
__device__ __forceinline__ void cp_commit() {
    asm volatile("cp.async.commit_group;");
}

__device__ __forceinline__ void ldm_x4(uint32_t* r, uint32_t addr) {
    asm volatile("ldmatrix.sync.aligned.m8n8.x4.shared.b16 {%0,%1,%2,%3}, [%4];"
                 : "=r"(r[0]), "=r"(r[1]), "=r"(r[2]), "=r"(r[3]) : "r"(addr));
}
__device__ __forceinline__ void ldm_x4t(uint32_t* r, uint32_t addr) {
    asm volatile("ldmatrix.sync.aligned.m8n8.x4.trans.shared.b16 {%0,%1,%2,%3}, [%4];"
                 : "=r"(r[0]), "=r"(r[1]), "=r"(r[2]), "=r"(r[3]) : "r"(addr));
}

__device__ __forceinline__ void mma_f16(float* c, const uint32_t* a, const uint32_t* b) {
    asm volatile(
        "mma.sync.aligned.m16n8k16.row.col.f32.f16.f16.f32 "
        "{%0,%1,%2,%3}, {%4,%5,%6,%7}, {%8,%9}, {%0,%1,%2,%3};"
        : "+f"(c[0]), "+f"(c[1]), "+f"(c[2]), "+f"(c[3])
        : "r"(a[0]), "r"(a[1]), "r"(a[2]), "r"(a[3]), "r"(b[0]), "r"(b[1]));
}

// ---------------------------------------------------------------------------
// Kernel 0: merged prep.
//   blocks [0, 512):  w (F,F,E) -> wt_h [kk][m], kk = n*128 + l
//   blocks [512, ..): nodes fp32 -> fp16 table (4 elements/thread)
// ---------------------------------------------------------------------------
#define PREP_W_BLOCKS 512
#define PREP_N_BLOCKS ((N_NODES * FDIM / 4 + 255) / 256)   // 6250

__global__ void prep_kernel(const float* __restrict__ w,
                            const float* __restrict__ nodes) {
    if (blockIdx.x < PREP_W_BLOCKS) {
        int idx = blockIdx.x * blockDim.x + threadIdx.x;
        if (idx >= KDIM * FDIM) return;
        int kk = idx >> 7;          // n*128 + l
        int m  = idx & 127;
        int n  = kk >> 7;
        int l  = kk & 127;
        wt_h[idx] = __float2half_rn(w[(l * FDIM + m) * EDIM + n]);
    } else {
        int idx = (blockIdx.x - PREP_W_BLOCKS) * blockDim.x + threadIdx.x;
        if (idx * 4 >= N_NODES * FDIM) return;
        const float4 v = *(const float4*)(nodes + idx * 4);
        __half2 a = __floats2half2_rn(v.x, v.y);
        __half2 b = __floats2half2_rn(v.z, v.w);
        *(uint2*)&nodes_h[(size_t)idx * 4] = make_uint2(*(uint32_t*)&a, *(uint32_t*)&b);
    }
}

// ---------------------------------------------------------------------------
// Kernel 1: stage 1 on tensor cores (proven R14 one-shot). One warp per node.
//   D[l, e] = sum_j X[j, l] * E[j, e]   (M=128, N=8, K=32)
// ---------------------------------------------------------------------------
#define S1_WSTRIDE 8960                       // 8KB X + 512B E + 128B nb + pad
#define S1_SMEM    (8 * S1_WSTRIDE)           // 70 KB -> 2 CTAs/SM

__global__ void __launch_bounds__(256, 2) stage1_tensor_kernel(
    const int* __restrict__ nlist,
    const float* __restrict__ edges)
{
    extern __shared__ __align__(256) char smem[];
    const int tid  = threadIdx.x;
    const int lane = tid & 31;
    const int wid  = tid >> 5;
    const int i    = blockIdx.x * 8 + wid;    // grid 6250 -> 50000 nodes

    char* wb = smem + wid * S1_WSTRIDE;
    const uint32_t xb  = smem_u32(wb);        // X tile: 32 rows x 256B (swizzled)
    const uint32_t ebs = xb + 8192;           // E tile: 32 rows x 16B
    int* nbp = (int*)(wb + 8704);             // 32 ints

    int nb = nlist[(size_t)i * KNBR + lane];
    nb = nb < 0 ? 0 : (nb >= N_NODES ? N_NODES - 1 : nb);
    nbp[lane] = nb;

    {
        const float4* e4 = (const float4*)(edges + (size_t)i * (KNBR * EDIM));
        const float4 a = e4[lane * 2 + 0];
        const float4 b = e4[lane * 2 + 1];
        __half2 h0 = __floats2half2_rn(a.x, a.y);
        __half2 h1 = __floats2half2_rn(a.z, a.w);
        __half2 h2 = __floats2half2_rn(b.x, b.y);
        __half2 h3 = __floats2half2_rn(b.z, b.w);
        *(uint4*)(wb + 8192 + lane * 16) =
            make_uint4(*(uint32_t*)&h0, *(uint32_t*)&h1, *(uint32_t*)&h2, *(uint32_t*)&h3);
    }
    __syncwarp();

#pragma unroll
    for (int it = 0; it < 16; it++) {
        const int jrow = it * 2 + (lane >> 4);
        const int c    = lane & 15;
        const uint32_t dst = xb + jrow * 256 + ((c ^ (jrow & 15)) << 4);
        cp_async16(dst, nodes_h + (size_t)nbp[jrow] * FDIM + c * 8);
    }
    cp_commit();
    asm volatile("cp.async.wait_group 0;");
    __syncwarp();

    uint32_t ebf[4];
    ldm_x4t(ebf, ebs + lane * 16);

    float acc[8][4];
#pragma unroll
    for (int mt = 0; mt < 8; mt++)
#pragma unroll
        for (int q = 0; q < 4; q++) acc[mt][q] = 0.f;

    const int krow_lo = (lane & 7) + ((lane >> 4) & 1) * 8;
    const int mc8     = (lane >> 3) & 1;

#pragma unroll
    for (int mt = 0; mt < 8; mt++) {
        const int ch = mt * 2 + mc8;
        uint32_t a0[4], a1[4];
        {
            const int kr = krow_lo;
            ldm_x4t(a0, xb + kr * 256 + ((ch ^ (kr & 15)) << 4));
        }
        {
            const int kr = krow_lo + 16;
            ldm_x4t(a1, xb + kr * 256 + ((ch ^ (kr & 15)) << 4));
        }
        mma_f16(acc[mt], a0, ebf + 0);
        mma_f16(acc[mt], a1, ebf + 2);
    }

    const size_t gb = (size_t)i * KDIM;
    const int e0 = (lane & 3) * 2;
#pragma unroll
    for (int mt = 0; mt < 8; mt++) {
        const int l0 = mt * 16 + (lane >> 2);
        g_h[gb + e0 * FDIM + l0]           = __float2half_rn(acc[mt][0]);
        g_h[gb + (e0 + 1) * FDIM + l0]     = __float2half_rn(acc[mt][1]);
        g_h[gb + e0 * FDIM + l0 + 8]       = __float2half_rn(acc[mt][2]);
        g_h[gb + (e0 + 1) * FDIM + l0 + 8] = __float2half_rn(acc[mt][3]);
    }
}

// ---------------------------------------------------------------------------
// Kernel 2: mma.sync fp16 GEMM, BM=64 x BN=128, KC=64 (16 iterations,
// halved sync overhead), 3-stage cp.async, 3 CTAs/SM, reversed tile order.
// Smem per stage: A 64x128B (8KB) + B 64x256B (16KB) = 24KB.
// Swizzles: A (8-chunk rows)  chunk' = c ^ (row & 7)
//           B (16-chunk rows) chunk' = c ^ (row & 15)
// ---------------------------------------------------------------------------
#define BM        64
#define KC        64
#define NKCHUNKS  (KDIM / KC)         // 16
#define OFF_A     0
#define OFF_B     8192
#define BUF_BYTES 24576               // 8K (A) + 16K (B)
#define NSTAGES   3
#define SMEM_DYN  (NSTAGES * BUF_BYTES)   // 72 KB
#define NBLOCKS_M ((N_NODES + BM - 1) / BM)   // 782

__global__ void __launch_bounds__(256, 3) stage2_mma_kernel(
    const float* __restrict__ inv_degree,
    float* __restrict__ out)
{
    extern __shared__ __align__(128) char smem[];
    const uint32_t sbase = smem_u32(smem);

    const int tid    = threadIdx.x;
    const int lane   = tid & 31;
    const int wid    = tid >> 5;
    const int warp_m = wid & 3;
    const int warp_n = wid >> 2;
    const int m0     = (NBLOCKS_M - 1 - blockIdx.x) * BM;

    float acc[8][4];
#pragma unroll
    for (int nt = 0; nt < 8; nt++)
#pragma unroll
        for (int q = 0; q < 4; q++) acc[nt][q] = 0.f;

    auto load_chunk = [&](int kc, int b) {
        if (kc < NKCHUNKS) {
            const uint32_t sb = sbase + b * BUF_BYTES;
            // A: 64 rows x 8 chunks = 512 chunks -> 2 per thread
#pragma unroll
            for (int it = 0; it < 2; it++) {
                const int ia  = tid + it * 256;
                const int row = ia >> 3;
                const int c   = ia & 7;
                const uint32_t so = row * 128 + ((c ^ (row & 7)) << 4);
                const size_t ge = (size_t)(m0 + row) * KDIM + kc * KC + c * 8;
                cp_async16(sb + OFF_A + so, g_h + ge);
            }
            // B: 64 rows x 16 chunks = 1024 chunks -> 4 per thread
#pragma unroll
            for (int it = 0; it < 4; it++) {
                const int ib  = tid + it * 256;
                const int row = ib >> 4;
                const int c   = ib & 15;
                const uint32_t so = row * 256 + ((c ^ (row & 15)) << 4);
                const size_t ge = (size_t)(kc * KC + row) * FDIM + c * 8;
                cp_async16(sb + OFF_B + so, wt_h + ge);
            }
        }
        cp_commit();
    };

    load_chunk(0, 0);
    load_chunk(1, 1);

#pragma unroll 1
    for (int kc = 0; kc < NKCHUNKS; kc++) {
        asm volatile("cp.async.wait_group 1;");
        __syncthreads();

        load_chunk(kc + 2, (kc + 2) % NSTAGES);

        const uint32_t sb = sbase + (kc % NSTAGES) * BUF_BYTES;

#pragma unroll
        for (int k16 = 0; k16 < 4; k16++) {
            uint32_t af[4];
            const int rA  = (lane & 7) + ((lane >> 3) & 1) * 8;
            const int kch = k16 * 2 + (lane >> 4);          // 0..7
            {
                const int row = warp_m * 16 + rA;
                const uint32_t off = row * 128 + ((kch ^ (row & 7)) << 4);
                ldm_x4(af, sb + OFF_A + off);
            }
            const int rB = k16 * 16 + (lane & 7) + ((lane >> 3) & 1) * 8;  // 0..63
#pragma unroll
            for (int nt16 = 0; nt16 < 4; nt16++) {
                const int nch = warp_n * 8 + nt16 * 2 + (lane >> 4);
                const uint32_t off = rB * 256 + ((nch ^ (rB & 15)) << 4);
                uint32_t bf[4];
                ldm_x4t(bf, sb + OFF_B + off);
                mma_f16(acc[nt16 * 2 + 0], af, bf + 0);
                mma_f16(acc[nt16 * 2 + 1], af, bf + 2);
            }
        }
    }

    {
        const int r0 = m0 + warp_m * 16 + (lane >> 2);
        const int r1 = r0 + 8;
        const float s0 = (r0 < N_NODES) ? inv_degree[r0] : 0.f;
        const float s1 = (r1 < N_NODES) ? inv_degree[r1] : 0.f;
#pragma unroll
        for (int nt = 0; nt < 8; nt++) {
            const int col = warp_n * 64 + nt * 8 + (lane & 3) * 2;
            if (r0 < N_NODES) {
                float2 o = make_float2(acc[nt][0] * s0, acc[nt][1] * s0);
                *(float2*)(out + (size_t)r0 * FDIM + col) = o;
            }
            if (r1 < N_NODES) {
                float2 o = make_float2(acc[nt][2] * s1, acc[nt][3] * s1);
                *(float2*)(out + (size_t)r1 * FDIM + col) = o;
            }
        }
    }
}

// ---------------------------------------------------------------------------
// Launch. Inputs identified BY ELEMENT COUNT (all five distinct).
// ---------------------------------------------------------------------------
extern "C" void kernel_launch(void* const* d_in, const int* in_sizes, int n_in,
                              void* d_out, int out_size) {
    const float* nodes      = nullptr;
    const int*   nlist      = nullptr;
    const float* edges      = nullptr;
    const float* inv_degree = nullptr;
    const float* w          = nullptr;

    for (int i = 0; i < n_in; i++) {
        switch (in_sizes[i]) {
            case 6400000:  nodes      = (const float*)d_in[i]; break;
            case 1600000:  nlist      = (const int*)d_in[i];   break;
            case 12800000: edges      = (const float*)d_in[i]; break;
            case 50000:    inv_degree = (const float*)d_in[i]; break;
            case 131072:   w          = (const float*)d_in[i]; break;
            default: break;
        }
    }
    if (!nodes || !nlist || !edges || !inv_degree || !w) return;

    float* out = (float*)d_out;

    cudaFuncSetAttribute(stage1_tensor_kernel,
                         cudaFuncAttributeMaxDynamicSharedMemorySize, S1_SMEM);
    cudaFuncSetAttribute(stage2_mma_kernel,
                         cudaFuncAttributeMaxDynamicSharedMemorySize, SMEM_DYN);

    prep_kernel<<<PREP_W_BLOCKS + PREP_N_BLOCKS, 256>>>(w, nodes);
    stage1_tensor_kernel<<<N_NODES / 8, 256, S1_SMEM>>>(nlist, edges);
    stage2_mma_kernel<<<NBLOCKS_M, 256, SMEM_DYN>>>(inv_degree, out);
}

// round 17
// speedup vs baseline: 1.7299x; 1.0708x over previous
#include <cuda_runtime.h>
#include <cuda_fp16.h>
#include <cstdint>
#include <cstddef>

// Problem constants
#define N_NODES 50000
#define N_PAD   50048
#define KNBR    32
#define FDIM    128
#define EDIM    8
#define KDIM    1024          // FDIM * EDIM

// G as fp16, rows [i][kk], kk = n*128 + l  (zero-init; rows >= 50000 stay 0)
__device__ __half g_h[(size_t)N_PAD * KDIM];   // 102.5 MB
// W rearranged to [kk][m] fp16
__device__ __half wt_h[KDIM * FDIM];
// fp16 copy of nodes (gather table, L2-resident 12.8 MB)
__device__ __half nodes_h[(size_t)N_NODES * FDIM];

// ---------------------------------------------------------------------------
// helpers
// ---------------------------------------------------------------------------
__device__ __forceinline__ uint32_t smem_u32(const void* p) {
    uint32_t a;
    asm("{ .reg .u64 t; cvta.to.shared.u64 t, %1; cvt.u32.u64 %0, t; }" : "=r"(a) : "l"(p));
    return a;
}

__device__ __forceinline__ void cp_async16(uint32_t dst, const void* src) {
    asm volatile("cp.async.cg.shared.global [%0], [%1], 16;" :: "r"(dst), "l"(src));
}
__device__ __forceinline__ void cp_commit() {
    asm volatile("cp.async.commit_group;");
}

__device__ __forceinline__ void ldm_x4(uint32_t* r, uint32_t addr) {
    asm volatile("ldmatrix.sync.aligned.m8n8.x4.shared.b16 {%0,%1,%2,%3}, [%4];"
                 : "=r"(r[0]), "=r"(r[1]), "=r"(r[2]), "=r"(r[3]) : "r"(addr));
}
__device__ __forceinline__ void ldm_x4t(uint32_t* r, uint32_t addr) {
    asm volatile("ldmatrix.sync.aligned.m8n8.x4.trans.shared.b16 {%0,%1,%2,%3}, [%4];"
                 : "=r"(r[0]), "=r"(r[1]), "=r"(r[2]), "=r"(r[3]) : "r"(addr));
}

__device__ __forceinline__ void mma_f16(float* c, const uint32_t* a, const uint32_t* b) {
    asm volatile(
        "mma.sync.aligned.m16n8k16.row.col.f32.f16.f16.f32 "
        "{%0,%1,%2,%3}, {%4,%5,%6,%7}, {%8,%9}, {%0,%1,%2,%3};"
        : "+f"(c[0]), "+f"(c[1]), "+f"(c[2]), "+f"(c[3])
        : "r"(a[0]), "r"(a[1]), "r"(a[2]), "r"(a[3]), "r"(b[0]), "r"(b[1]));
}

// ---------------------------------------------------------------------------
// Kernel 0: merged prep.
//   blocks [0, 512):  w (F,F,E) -> wt_h [kk][m], kk = n*128 + l
//   blocks [512, ..): nodes fp32 -> fp16 table (4 elements/thread)
// ---------------------------------------------------------------------------
#define PREP_W_BLOCKS 512
#define PREP_N_BLOCKS ((N_NODES * FDIM / 4 + 255) / 256)   // 6250

__global__ void prep_kernel(const float* __restrict__ w,
                            const float* __restrict__ nodes) {
    if (blockIdx.x < PREP_W_BLOCKS) {
        int idx = blockIdx.x * blockDim.x + threadIdx.x;
        if (idx >= KDIM * FDIM) return;
        int kk = idx >> 7;          // n*128 + l
        int m  = idx & 127;
        int n  = kk >> 7;
        int l  = kk & 127;
        wt_h[idx] = __float2half_rn(w[(l * FDIM + m) * EDIM + n]);
    } else {
        int idx = (blockIdx.x - PREP_W_BLOCKS) * blockDim.x + threadIdx.x;
        if (idx * 4 >= N_NODES * FDIM) return;
        const float4 v = *(const float4*)(nodes + idx * 4);
        __half2 a = __floats2half2_rn(v.x, v.y);
        __half2 b = __floats2half2_rn(v.z, v.w);
        *(uint2*)&nodes_h[(size_t)idx * 4] = make_uint2(*(uint32_t*)&a, *(uint32_t*)&b);
    }
}

// ---------------------------------------------------------------------------
// Kernel 1: stage 1 on tensor cores (proven R14 one-shot). One warp per node.
//   D[l, e] = sum_j X[j, l] * E[j, e]   (M=128, N=8, K=32)
// ---------------------------------------------------------------------------
#define S1_WSTRIDE 8960                       // 8KB X + 512B E + 128B nb + pad
#define S1_SMEM    (8 * S1_WSTRIDE)           // 70 KB -> 2 CTAs/SM

__global__ void __launch_bounds__(256, 2) stage1_tensor_kernel(
    const int* __restrict__ nlist,
    const float* __restrict__ edges)
{
    extern __shared__ __align__(256) char smem[];
    const int tid  = threadIdx.x;
    const int lane = tid & 31;
    const int wid  = tid >> 5;
    const int i    = blockIdx.x * 8 + wid;    // grid 6250 -> 50000 nodes

    char* wb = smem + wid * S1_WSTRIDE;
    const uint32_t xb  = smem_u32(wb);        // X tile: 32 rows x 256B (swizzled)
    const uint32_t ebs = xb + 8192;           // E tile: 32 rows x 16B
    int* nbp = (int*)(wb + 8704);             // 32 ints

    int nb = nlist[(size_t)i * KNBR + lane];
    nb = nb < 0 ? 0 : (nb >= N_NODES ? N_NODES - 1 : nb);
    nbp[lane] = nb;

    {
        const float4* e4 = (const float4*)(edges + (size_t)i * (KNBR * EDIM));
        const float4 a = e4[lane * 2 + 0];
        const float4 b = e4[lane * 2 + 1];
        __half2 h0 = __floats2half2_rn(a.x, a.y);
        __half2 h1 = __floats2half2_rn(a.z, a.w);
        __half2 h2 = __floats2half2_rn(b.x, b.y);
        __half2 h3 = __floats2half2_rn(b.z, b.w);
        *(uint4*)(wb + 8192 + lane * 16) =
            make_uint4(*(uint32_t*)&h0, *(uint32_t*)&h1, *(uint32_t*)&h2, *(uint32_t*)&h3);
    }
    __syncwarp();

#pragma unroll
    for (int it = 0; it < 16; it++) {
        const int jrow = it * 2 + (lane >> 4);
        const int c    = lane & 15;
        const uint32_t dst = xb + jrow * 256 + ((c ^ (jrow & 15)) << 4);
        cp_async16(dst, nodes_h + (size_t)nbp[jrow] * FDIM + c * 8);
    }
    cp_commit();
    asm volatile("cp.async.wait_group 0;");
    __syncwarp();

    uint32_t ebf[4];
    ldm_x4t(ebf, ebs + lane * 16);

    float acc[8][4];
#pragma unroll
    for (int mt = 0; mt < 8; mt++)
#pragma unroll
        for (int q = 0; q < 4; q++) acc[mt][q] = 0.f;

    const int krow_lo = (lane & 7) + ((lane >> 4) & 1) * 8;
    const int mc8     = (lane >> 3) & 1;

#pragma unroll
    for (int mt = 0; mt < 8; mt++) {
        const int ch = mt * 2 + mc8;
        uint32_t a0[4], a1[4];
        {
            const int kr = krow_lo;
            ldm_x4t(a0, xb + kr * 256 + ((ch ^ (kr & 15)) << 4));
        }
        {
            const int kr = krow_lo + 16;
            ldm_x4t(a1, xb + kr * 256 + ((ch ^ (kr & 15)) << 4));
        }
        mma_f16(acc[mt], a0, ebf + 0);
        mma_f16(acc[mt], a1, ebf + 2);
    }

    const size_t gb = (size_t)i * KDIM;
    const int e0 = (lane & 3) * 2;
#pragma unroll
    for (int mt = 0; mt < 8; mt++) {
        const int l0 = mt * 16 + (lane >> 2);
        g_h[gb + e0 * FDIM + l0]           = __float2half_rn(acc[mt][0]);
        g_h[gb + (e0 + 1) * FDIM + l0]     = __float2half_rn(acc[mt][1]);
        g_h[gb + e0 * FDIM + l0 + 8]       = __float2half_rn(acc[mt][2]);
        g_h[gb + (e0 + 1) * FDIM + l0 + 8] = __float2half_rn(acc[mt][3]);
    }
}

// ---------------------------------------------------------------------------
// Kernel 2: mma.sync fp16 GEMM, BM=128 x BN=128 (halves W L1 traffic vs
// BM=64: 200 MB -> 100 MB), KC=32, 4-stage cp.async, 2 CTAs/SM.
// Structure = proven R6 BM=128 skeleton; inner product = proven fp16 single.
// 8 warps (4m x 2n), warp tile 32x64.
// Smem swizzles:
//   A tile [128][32] fp16 (64B rows, 4 chunks):  chunk' = c ^ ((row>>1)&3)
//   B tile [32][128] fp16 (256B rows, 16 chunks): chunk' = c ^ (row&15)
// ---------------------------------------------------------------------------
#define BM        128
#define KC        32
#define NKCHUNKS  (KDIM / KC)         // 32
#define OFF_A     0
#define OFF_B     8192
#define BUF_BYTES 16384               // 8K (A) + 8K (B)
#define NSTAGES   4
#define SMEM_DYN  (NSTAGES * BUF_BYTES)   // 64 KB
#define NBLOCKS_M ((N_NODES + BM - 1) / BM)   // 391

__global__ void __launch_bounds__(256, 2) stage2_mma_kernel(
    const float* __restrict__ inv_degree,
    float* __restrict__ out)
{
    extern __shared__ __align__(128) char smem[];
    const uint32_t sbase = smem_u32(smem);

    const int tid    = threadIdx.x;
    const int lane   = tid & 31;
    const int wid    = tid >> 5;
    const int warp_m = wid & 3;        // m offset 32*warp_m
    const int warp_n = wid >> 2;       // n offset 64*warp_n
    const int m0     = (NBLOCKS_M - 1 - blockIdx.x) * BM;

    float acc[2][8][4];
#pragma unroll
    for (int mt = 0; mt < 2; mt++)
#pragma unroll
        for (int nt = 0; nt < 8; nt++)
#pragma unroll
            for (int q = 0; q < 4; q++) acc[mt][nt][q] = 0.f;

    auto load_chunk = [&](int kc, int b) {
        if (kc < NKCHUNKS) {
            const uint32_t sb = sbase + b * BUF_BYTES;
            // A: 128 rows x 4 chunks = 512 chunks -> 2 per thread
#pragma unroll
            for (int it = 0; it < 2; it++) {
                const int ca  = tid + it * 256;
                const int row = ca >> 2;
                const int c   = ca & 3;
                const uint32_t so = row * 64 + ((c ^ ((row >> 1) & 3)) << 4);
                const size_t ge = (size_t)(m0 + row) * KDIM + kc * KC + c * 8;
                cp_async16(sb + OFF_A + so, g_h + ge);
            }
            // B: 32 rows x 16 chunks = 512 chunks -> 2 per thread
#pragma unroll
            for (int it = 0; it < 2; it++) {
                const int cb  = tid + it * 256;
                const int row = cb >> 4;
                const int c   = cb & 15;
                const uint32_t so = row * 256 + ((c ^ (row & 15)) << 4);
                const size_t ge = (size_t)(kc * KC + row) * FDIM + c * 8;
                cp_async16(sb + OFF_B + so, wt_h + ge);
            }
        }
        cp_commit();
    };

    load_chunk(0, 0);
    load_chunk(1, 1);
    load_chunk(2, 2);

#pragma unroll 1
    for (int kc = 0; kc < NKCHUNKS; kc++) {
        asm volatile("cp.async.wait_group 2;");
        __syncthreads();

        load_chunk(kc + 3, (kc + 3) % NSTAGES);

        const uint32_t sb = sbase + (kc % NSTAGES) * BUF_BYTES;

#pragma unroll
        for (int k16 = 0; k16 < 2; k16++) {
            // A fragments: two m16 tiles
            uint32_t af[2][4];
            const int rA  = (lane & 7) + ((lane >> 3) & 1) * 8;
            const int kch = k16 * 2 + (lane >> 4);
#pragma unroll
            for (int mt = 0; mt < 2; mt++) {
                const int row = warp_m * 32 + mt * 16 + rA;
                const uint32_t off = row * 64 + ((kch ^ ((row >> 1) & 3)) << 4);
                ldm_x4(af[mt], sb + OFF_A + off);
            }
            const int rB = k16 * 16 + (lane & 7) + ((lane >> 3) & 1) * 8;
#pragma unroll
            for (int nt16 = 0; nt16 < 4; nt16++) {
                const int nch = warp_n * 8 + nt16 * 2 + (lane >> 4);
                const uint32_t off = rB * 256 + ((nch ^ (rB & 15)) << 4);
                uint32_t bf[4];
                ldm_x4t(bf, sb + OFF_B + off);
#pragma unroll
                for (int mt = 0; mt < 2; mt++) {
                    mma_f16(acc[mt][nt16 * 2 + 0], af[mt], bf + 0);
                    mma_f16(acc[mt][nt16 * 2 + 1], af[mt], bf + 2);
                }
            }
        }
    }

    // ---- epilogue: scale + store ----
#pragma unroll
    for (int mt = 0; mt < 2; mt++) {
        const int r0 = m0 + warp_m * 32 + mt * 16 + (lane >> 2);
        const int r1 = r0 + 8;
        const float s0 = (r0 < N_NODES) ? inv_degree[r0] : 0.f;
        const float s1 = (r1 < N_NODES) ? inv_degree[r1] : 0.f;
#pragma unroll
        for (int nt = 0; nt < 8; nt++) {
            const int col = warp_n * 64 + nt * 8 + (lane & 3) * 2;
            if (r0 < N_NODES) {
                float2 o = make_float2(acc[mt][nt][0] * s0, acc[mt][nt][1] * s0);
                *(float2*)(out + (size_t)r0 * FDIM + col) = o;
            }
            if (r1 < N_NODES) {
                float2 o = make_float2(acc[mt][nt][2] * s1, acc[mt][nt][3] * s1);
                *(float2*)(out + (size_t)r1 * FDIM + col) = o;
            }
        }
    }
}

// ---------------------------------------------------------------------------
// Launch. Inputs identified BY ELEMENT COUNT (all five distinct).
// ---------------------------------------------------------------------------
extern "C" void kernel_launch(void* const* d_in, const int* in_sizes, int n_in,
                              void* d_out, int out_size) {
    const float* nodes      = nullptr;
    const int*   nlist      = nullptr;
    const float* edges      = nullptr;
    const float* inv_degree = nullptr;
    const float* w          = nullptr;

    for (int i = 0; i < n_in; i++) {
        switch (in_sizes[i]) {
            case 6400000:  nodes      = (const float*)d_in[i]; break;
            case 1600000:  nlist      = (const int*)d_in[i];   break;
            case 12800000: edges      = (const float*)d_in[i]; break;
            case 50000:    inv_degree = (const float*)d_in[i]; break;
            case 131072:   w          = (const float*)d_in[i]; break;
            default: break;
        }
    }
    if (!nodes || !nlist || !edges || !inv_degree || !w) return;

    float* out = (float*)d_out;

    cudaFuncSetAttribute(stage1_tensor_kernel,
                         cudaFuncAttributeMaxDynamicSharedMemorySize, S1_SMEM);
    cudaFuncSetAttribute(stage2_mma_kernel,
                         cudaFuncAttributeMaxDynamicSharedMemorySize, SMEM_DYN);

    prep_kernel<<<PREP_W_BLOCKS + PREP_N_BLOCKS, 256>>>(w, nodes);
    stage1_tensor_kernel<<<N_NODES / 8, 256, S1_SMEM>>>(nlist, edges);
    stage2_mma_kernel<<<NBLOCKS_M, 256, SMEM_DYN>>>(inv_degree, out);
}